// round 9
// baseline (speedup 1.0000x reference)
#include <cuda_runtime.h>
#include <cuda_fp16.h>
#include <math.h>
#include <stdint.h>

#define DIMC 1024
#define NH 16
#define HD 64
#define BATCH 4
#define SEQ 2048
#define MROWS (BATCH*SEQ)   // 8192
#define QSCALE 0.1803368801111204f   // log2(e)/8

// Scratch (device globals — no runtime allocation)
__device__ __half g_xh[(size_t)MROWS*DIMC];
__device__ __half g_wqh[(size_t)DIMC*3*DIMC];
__device__ __half g_woh[(size_t)DIMC*DIMC];
__device__ __half g_qh[(size_t)BATCH*NH*SEQ*HD];  // [B,H,T,D], pre-scaled by QSCALE
__device__ __half g_kh[(size_t)BATCH*NH*SEQ*HD];
__device__ __half g_vh[(size_t)BATCH*NH*SEQ*HD];
__device__ __half g_oh[(size_t)BATCH*SEQ*DIMC];   // attention out [B,T,C]

// ---------------------------------------------------------------------------
__device__ __forceinline__ void cp16(void* s, const void* g) {
    uint32_t a = (uint32_t)__cvta_generic_to_shared(s);
    asm volatile("cp.async.cg.shared.global [%0], [%1], 16;" :: "r"(a), "l"(g));
}
#define CP_COMMIT() asm volatile("cp.async.commit_group;" ::: "memory")
#define CP_WAIT0()  asm volatile("cp.async.wait_group 0;" ::: "memory")
#define CP_WAIT1()  asm volatile("cp.async.wait_group 1;" ::: "memory")

__device__ __forceinline__ void mma16(float c[4], const uint32_t a[4],
                                      uint32_t b0, uint32_t b1) {
    asm volatile(
        "mma.sync.aligned.m16n8k16.row.col.f32.f16.f16.f32 "
        "{%0,%1,%2,%3}, {%4,%5,%6,%7}, {%8,%9}, {%0,%1,%2,%3};\n"
        : "+f"(c[0]), "+f"(c[1]), "+f"(c[2]), "+f"(c[3])
        : "r"(a[0]), "r"(a[1]), "r"(a[2]), "r"(a[3]), "r"(b0), "r"(b1));
}
// f16-accumulate variant: C/D are 2x f16x2 regs
__device__ __forceinline__ void mma16h(uint32_t c[2], const uint32_t a[4],
                                       uint32_t b0, uint32_t b1) {
    asm volatile(
        "mma.sync.aligned.m16n8k16.row.col.f16.f16.f16.f16 "
        "{%0,%1}, {%2,%3,%4,%5}, {%6,%7}, {%0,%1};\n"
        : "+r"(c[0]), "+r"(c[1])
        : "r"(a[0]), "r"(a[1]), "r"(a[2]), "r"(a[3]), "r"(b0), "r"(b1));
}
__device__ __forceinline__ void ldsm4(uint32_t r[4], const void* p) {
    uint32_t a = (uint32_t)__cvta_generic_to_shared(p);
    asm volatile("ldmatrix.sync.aligned.m8n8.x4.shared.b16 {%0,%1,%2,%3}, [%4];"
        : "=r"(r[0]), "=r"(r[1]), "=r"(r[2]), "=r"(r[3]) : "r"(a));
}
__device__ __forceinline__ void ldsm4t(uint32_t r[4], const void* p) {
    uint32_t a = (uint32_t)__cvta_generic_to_shared(p);
    asm volatile("ldmatrix.sync.aligned.m8n8.x4.trans.shared.b16 {%0,%1,%2,%3}, [%4];"
        : "=r"(r[0]), "=r"(r[1]), "=r"(r[2]), "=r"(r[3]) : "r"(a));
}
__device__ __forceinline__ uint32_t pexp2(float lo, float hi) {
    uint32_t h, r;
    asm("cvt.rn.f16x2.f32 %0, %1, %2;" : "=r"(h) : "f"(hi), "f"(lo));
    asm("ex2.approx.f16x2 %0, %1;" : "=r"(r) : "r"(h));
    return r;
}
__device__ __forceinline__ float fexp2(float x) {
    float r; asm("ex2.approx.f32 %0, %1;" : "=f"(r) : "f"(x)); return r;
}

// ---------------------------------------------------------------------------
// fp32 -> fp16 conversion pre-pass (x, W_qkv, W_out)
// ---------------------------------------------------------------------------
__global__ void cvt_kernel(const float* __restrict__ x, const float* __restrict__ wq,
                           const float* __restrict__ wo) {
    const int XN4 = MROWS * DIMC / 4;
    const int WQ4 = DIMC * 3 * DIMC / 4;
    const int WO4 = DIMC * DIMC / 4;
    const int total = XN4 + WQ4 + WO4;
    for (int i = blockIdx.x * blockDim.x + threadIdx.x; i < total;
         i += gridDim.x * blockDim.x) {
        const float4* src; __half2* dst; int j;
        if (i < XN4)            { src = (const float4*)x;  dst = (__half2*)g_xh;  j = i; }
        else if (i < XN4 + WQ4) { src = (const float4*)wq; dst = (__half2*)g_wqh; j = i - XN4; }
        else                    { src = (const float4*)wo; dst = (__half2*)g_woh; j = i - XN4 - WQ4; }
        float4 v = src[j];
        dst[2 * j]     = __floats2half2_rn(v.x, v.y);
        dst[2 * j + 1] = __floats2half2_rn(v.z, v.w);
    }
}

// ---------------------------------------------------------------------------
// fp16 mma GEMM: C[M,N] = A[M,K] @ W[K,N] + bias
// CTA 128x128, 128 threads (4 warps as 2m x 2n), warp tile 64x64.
// BK=64, 3-stage cp.async, double-buffered ldsm fragments.
// HACC=1: f16 accumulators promoted to fp32 every K=32 (2 HMMA).
// ---------------------------------------------------------------------------
#define AS_STG (128 * 72)           // halves per A stage (pad 64+8)
#define BS_STG (64 * 136)           // halves per B stage (pad 128+8)
#define GEMM_SMEM ((3 * AS_STG + 3 * BS_STG) * 2)   // 107520 bytes

template<int SCATTER, int HACC>
__global__ __launch_bounds__(128, 2) void gemm_h(
    const __half* __restrict__ Ah, const __half* __restrict__ Wh,
    const float* __restrict__ bias, float* __restrict__ C, int N, int K)
{
    extern __shared__ __align__(16) __half sm[];
    __half* As = sm;                   // [3][128][72]
    __half* Bs = sm + 3 * AS_STG;      // [3][64][136]

    const int tid  = threadIdx.x;
    const int wid  = tid >> 5;
    const int lane = tid & 31;
    const int gid  = lane >> 2;
    const int tig  = lane & 3;
    const int sel  = lane >> 3;
    const int lr   = lane & 7;
    const int wm   = wid & 1;     // 0..1
    const int wn   = wid >> 1;    // 0..1
    const int mBase = blockIdx.y * 128;
    const int nBase = blockIdx.x * 128;

    float acc[4][8][4];
    #pragma unroll
    for (int mt = 0; mt < 4; mt++)
        #pragma unroll
        for (int nt = 0; nt < 8; nt++)
            #pragma unroll
            for (int i = 0; i < 4; i++) acc[mt][nt][i] = 0.0f;

    uint32_t acch[4][8][2];
    if (HACC) {
        #pragma unroll
        for (int mt = 0; mt < 4; mt++)
            #pragma unroll
            for (int nt = 0; nt < 8; nt++) { acch[mt][nt][0] = 0u; acch[mt][nt][1] = 0u; }
    }

    const int NC = K / 64;   // 16

    #define ISSUE(c) do { \
        if ((c) < NC) { \
            const int kt = (c) * 64; \
            const int st = (c) % 3; \
            _Pragma("unroll") \
            for (int l = 0; l < 8; l++) { \
                const int o = tid + 128 * l; \
                cp16(&As[st * AS_STG + (o >> 3) * 72 + (o & 7) * 8], \
                     Ah + (size_t)(mBase + (o >> 3)) * K + kt + (o & 7) * 8); \
            } \
            _Pragma("unroll") \
            for (int l = 0; l < 8; l++) { \
                const int o = tid + 128 * l; \
                cp16(&Bs[st * BS_STG + (o >> 4) * 136 + (o & 15) * 8], \
                     Wh + (size_t)(kt + (o >> 4)) * N + nBase + (o & 15) * 8); \
            } \
        } \
        CP_COMMIT(); \
    } while (0)

    #define LDFRAG(s, kk, AF, BF) do { \
        _Pragma("unroll") \
        for (int mt = 0; mt < 4; mt++) \
            ldsm4(AF[mt], &As[(s) * AS_STG \
                              + (wm * 64 + mt * 16 + ((sel & 1) << 3) + lr) * 72 \
                              + (kk) * 16 + (sel >> 1) * 8]); \
        _Pragma("unroll") \
        for (int nb = 0; nb < 4; nb++) \
            ldsm4t(BF[nb], &Bs[(s) * BS_STG \
                               + ((kk) * 16 + (sel & 1) * 8 + lr) * 136 \
                               + wn * 64 + nb * 16 + (sel >> 1) * 8]); \
    } while (0)

    #define MMA32F(AF, BF) do { \
        _Pragma("unroll") \
        for (int mt = 0; mt < 4; mt++) \
            _Pragma("unroll") \
            for (int nb = 0; nb < 4; nb++) { \
                mma16(acc[mt][2 * nb],     AF[mt], BF[nb][0], BF[nb][1]); \
                mma16(acc[mt][2 * nb + 1], AF[mt], BF[nb][2], BF[nb][3]); \
            } \
    } while (0)

    #define MMA32H(AF, BF) do { \
        _Pragma("unroll") \
        for (int mt = 0; mt < 4; mt++) \
            _Pragma("unroll") \
            for (int nb = 0; nb < 4; nb++) { \
                mma16h(acch[mt][2 * nb],     AF[mt], BF[nb][0], BF[nb][1]); \
                mma16h(acch[mt][2 * nb + 1], AF[mt], BF[nb][2], BF[nb][3]); \
            } \
    } while (0)

    // Promote f16 accumulators into fp32 masters and clear
    #define PROMOTE() do { \
        _Pragma("unroll") \
        for (int mt = 0; mt < 4; mt++) \
            _Pragma("unroll") \
            for (int nt = 0; nt < 8; nt++) { \
                float2 p0 = __half22float2(*(__half2*)&acch[mt][nt][0]); \
                float2 p1 = __half22float2(*(__half2*)&acch[mt][nt][1]); \
                acc[mt][nt][0] += p0.x; acc[mt][nt][1] += p0.y; \
                acc[mt][nt][2] += p1.x; acc[mt][nt][3] += p1.y; \
                acch[mt][nt][0] = 0u;   acch[mt][nt][1] = 0u; \
            } \
    } while (0)

    // Prologue: stages 0..1 in flight
    ISSUE(0); ISSUE(1);

    uint32_t af[2][4][4], bf[2][4][4];

    for (int c = 0; c < NC; c++) {
        const int s = c % 3;
        CP_WAIT1();            // stage c complete (pending = c+1)
        __syncthreads();       // all warps done reading slot being re-issued
        ISSUE(c + 2);
        LDFRAG(s, 0, af[0], bf[0]);
        #pragma unroll
        for (int kk = 0; kk < 4; kk++) {
            const int cur = kk & 1;
            if (kk < 3) LDFRAG(s, kk + 1, af[cur ^ 1], bf[cur ^ 1]);
            if (HACC) {
                MMA32H(af[cur], bf[cur]);
                if (kk & 1) PROMOTE();   // every K=32
            } else {
                MMA32F(af[cur], bf[cur]);
            }
        }
    }
    #undef ISSUE
    #undef LDFRAG
    #undef MMA32F
    #undef MMA32H
    #undef PROMOTE

    // Epilogue
    #pragma unroll
    for (int mt = 0; mt < 4; mt++) {
        const int m0 = mBase + wm * 64 + mt * 16 + gid;
        #pragma unroll
        for (int nt = 0; nt < 8; nt++) {
            const int n = nBase + wn * 64 + nt * 8 + tig * 2;
            const float b0 = bias[n], b1 = bias[n + 1];
            float v0 = acc[mt][nt][0] + b0, v1 = acc[mt][nt][1] + b1;
            float v2 = acc[mt][nt][2] + b0, v3 = acc[mt][nt][3] + b1;
            if (SCATTER) {
                const int sec = n >> 10;
                const int cc  = n & 1023;
                const int h   = cc >> 6;
                const int d   = cc & 63;
                if (sec == 0) { v0 *= QSCALE; v1 *= QSCALE; v2 *= QSCALE; v3 *= QSCALE; }
                __half* dst = (sec == 0) ? g_qh : (sec == 1) ? g_kh : g_vh;
                const int m1 = m0 + 8;
                *(__half2*)&dst[(((size_t)(m0 >> 11) * NH + h) * SEQ + (m0 & (SEQ - 1))) * HD + d]
                    = __floats2half2_rn(v0, v1);
                *(__half2*)&dst[(((size_t)(m1 >> 11) * NH + h) * SEQ + (m1 & (SEQ - 1))) * HD + d]
                    = __floats2half2_rn(v2, v3);
            } else {
                *(float2*)&C[(size_t)m0 * N + n]       = make_float2(v0, v1);
                *(float2*)&C[(size_t)(m0 + 8) * N + n] = make_float2(v2, v3);
            }
        }
    }
}

// ---------------------------------------------------------------------------
// Causal flash attention, fp16 mma. CTA 256 threads (8 warps), BQ=128, BK=64.
// 3-stage cp.async K/V pipeline, ONE __syncthreads per tile. (unchanged)
// ---------------------------------------------------------------------------
#define KV_STG (64 * 72)   // halves per stage per array
#define FLASH_SMEM ((3 * KV_STG + 3 * KV_STG) * 2)   // 55296 bytes

__global__ __launch_bounds__(256, 2) void flash_h()
{
    extern __shared__ __align__(16) __half fsm[];
    __half* Ks = fsm;                 // [3][64][72]
    __half* Vs = fsm + 3 * KV_STG;    // [3][64][72]

    const int tid  = threadIdx.x;
    const int warp = tid >> 5;
    const int lane = tid & 31;
    const int gid  = lane >> 2;
    const int tig  = lane & 3;
    const int sel  = lane >> 3;
    const int lr   = lane & 7;
    const int bh = blockIdx.y;
    const int bb = bh >> 4;
    const int h  = bh & 15;
    const int q0 = blockIdx.x * 128;

    const __half* Qg = g_qh + (size_t)bh * SEQ * HD;
    const __half* Kg = g_kh + (size_t)bh * SEQ * HD;
    const __half* Vg = g_vh + (size_t)bh * SEQ * HD;

    // Stage Q (128 rows) into Ks stages 0-1, pull fragments, then release
    #pragma unroll
    for (int l = 0; l < 4; l++) {
        const int o = tid + 256 * l;
        const int row = o >> 3, seg = o & 7;
        cp16(&Ks[(row >> 6) * KV_STG + (row & 63) * 72 + seg * 8],
             Qg + (size_t)(q0 + row) * HD + seg * 8);
    }
    CP_COMMIT(); CP_WAIT0();
    __syncthreads();

    uint32_t qf[4][4];
    {
        const int rl = warp * 16 + ((sel & 1) << 3) + lr;  // 0..127
        #pragma unroll
        for (int kk = 0; kk < 4; kk++)
            ldsm4(qf[kk], &Ks[(rl >> 6) * KV_STG + (rl & 63) * 72
                              + kk * 16 + (sel >> 1) * 8]);
    }
    __syncthreads();

    float o_[8][4], lac[4];
    #pragma unroll
    for (int nt = 0; nt < 8; nt++)
        #pragma unroll
        for (int i = 0; i < 4; i++) o_[nt][i] = 0.0f;
    #pragma unroll
    for (int i = 0; i < 4; i++) lac[i] = 0.0f;
    float m0 = -1e30f, m1 = -1e30f;

    const int nT = (blockIdx.x + 1) * 2;

    #define ISSUE_KV(jt) do { \
        if ((jt) < nT) { \
            const int k0g = (jt) * 64; \
            const int st = (jt) % 3; \
            _Pragma("unroll") \
            for (int l = 0; l < 2; l++) { \
                const int o = tid + 256 * l; \
                const int row = o >> 3, seg = o & 7; \
                cp16(&Ks[st * KV_STG + row * 72 + seg * 8], \
                     Kg + (size_t)(k0g + row) * HD + seg * 8); \
            } \
            _Pragma("unroll") \
            for (int l = 0; l < 2; l++) { \
                const int o = tid + 256 * l; \
                const int row = o >> 3, seg = o & 7; \
                cp16(&Vs[st * KV_STG + row * 72 + seg * 8], \
                     Vg + (size_t)(k0g + row) * HD + seg * 8); \
            } \
        } \
        CP_COMMIT(); \
    } while (0)

    ISSUE_KV(0); ISSUE_KV(1);

    for (int jt = 0; jt < nT; jt++) {
        const int s = jt % 3;
        CP_WAIT1();            // tile jt complete (pending = jt+1)
        __syncthreads();       // readers of re-issued slot are done
        ISSUE_KV(jt + 2);

        // warps 0-3 (q rows q0..q0+63) skip the final k-tile entirely
        const bool act = !(warp < 4 && jt == nT - 1);
        if (act) {
            float sv[8][4];
            #pragma unroll
            for (int nt = 0; nt < 8; nt++)
                #pragma unroll
                for (int i = 0; i < 4; i++) sv[nt][i] = 0.0f;

            #pragma unroll
            for (int kk = 0; kk < 4; kk++)
                #pragma unroll
                for (int nb = 0; nb < 4; nb++) {
                    uint32_t kf[4];
                    ldsm4(kf, &Ks[s * KV_STG
                                  + (nb * 16 + ((sel >> 1) << 3) + lr) * 72
                                  + kk * 16 + (sel & 1) * 8]);
                    mma16(sv[2 * nb],     qf[kk], kf[0], kf[1]);
                    mma16(sv[2 * nb + 1], qf[kk], kf[2], kf[3]);
                }

            const bool diag = (warp < 4) ? (jt == nT - 2) : (jt == nT - 1);
            if (diag) {
                const int qr = q0 + warp * 16 + gid;
                const int k0g = jt * 64;
                #pragma unroll
                for (int nt = 0; nt < 8; nt++) {
                    const int kc = k0g + nt * 8 + tig * 2;
                    if (kc > qr)         sv[nt][0] = -1e30f;
                    if (kc + 1 > qr)     sv[nt][1] = -1e30f;
                    if (kc > qr + 8)     sv[nt][2] = -1e30f;
                    if (kc + 1 > qr + 8) sv[nt][3] = -1e30f;
                }
            }

            float mx0 = -1e30f, mx1 = -1e30f;
            #pragma unroll
            for (int nt = 0; nt < 8; nt++) {
                mx0 = fmaxf(mx0, fmaxf(sv[nt][0], sv[nt][1]));
                mx1 = fmaxf(mx1, fmaxf(sv[nt][2], sv[nt][3]));
            }
            mx0 = fmaxf(mx0, __shfl_xor_sync(0xffffffffu, mx0, 1));
            mx0 = fmaxf(mx0, __shfl_xor_sync(0xffffffffu, mx0, 2));
            mx1 = fmaxf(mx1, __shfl_xor_sync(0xffffffffu, mx1, 1));
            mx1 = fmaxf(mx1, __shfl_xor_sync(0xffffffffu, mx1, 2));

            const float mn0 = fmaxf(m0, mx0);
            const float mn1 = fmaxf(m1, mx1);
            const float al0 = fexp2(m0 - mn0);
            const float al1 = fexp2(m1 - mn1);
            m0 = mn0; m1 = mn1;

            uint32_t pu[8][2];
            #pragma unroll
            for (int nt = 0; nt < 8; nt++) {
                pu[nt][0] = pexp2(sv[nt][0] - mn0, sv[nt][1] - mn0);
                pu[nt][1] = pexp2(sv[nt][2] - mn1, sv[nt][3] - mn1);
            }

            #pragma unroll
            for (int nt = 0; nt < 8; nt++) {
                o_[nt][0] *= al0; o_[nt][1] *= al0;
                o_[nt][2] *= al1; o_[nt][3] *= al1;
            }
            lac[0] *= al0; lac[1] *= al0; lac[2] *= al1; lac[3] *= al1;

            const uint32_t ones = 0x3C003C00u;
            #pragma unroll
            for (int kk = 0; kk < 4; kk++) {
                const uint32_t pa[4] = {pu[2 * kk][0], pu[2 * kk][1],
                                        pu[2 * kk + 1][0], pu[2 * kk + 1][1]};
                mma16(lac, pa, ones, ones);
                #pragma unroll
                for (int nb = 0; nb < 4; nb++) {
                    uint32_t vf[4];
                    ldsm4t(vf, &Vs[s * KV_STG
                                   + (kk * 16 + (sel & 1) * 8 + lr) * 72
                                   + nb * 16 + (sel >> 1) * 8]);
                    mma16(o_[2 * nb],     pa, vf[0], vf[1]);
                    mma16(o_[2 * nb + 1], pa, vf[2], vf[3]);
                }
            }
        }
    }
    #undef ISSUE_KV

    // Epilogue
    const float inv0 = 1.0f / lac[0];
    const float inv1 = 1.0f / lac[2];
    const int qr = q0 + warp * 16 + gid;
    __half* dst0 = g_oh + ((size_t)bb * SEQ + qr) * DIMC + h * HD;
    __half* dst1 = g_oh + ((size_t)bb * SEQ + qr + 8) * DIMC + h * HD;
    #pragma unroll
    for (int nt = 0; nt < 8; nt++) {
        const int d = nt * 8 + tig * 2;
        *(__half2*)&dst0[d] = __floats2half2_rn(o_[nt][0] * inv0, o_[nt][1] * inv0);
        *(__half2*)&dst1[d] = __floats2half2_rn(o_[nt][2] * inv1, o_[nt][3] * inv1);
    }
}

// ---------------------------------------------------------------------------
extern "C" void kernel_launch(void* const* d_in, const int* in_sizes, int n_in,
                              void* d_out, int out_size)
{
    const float* x     = (const float*)d_in[0];
    const float* W_qkv = (const float*)d_in[1];
    const float* b_qkv = (const float*)d_in[2];
    const float* W_out = (const float*)d_in[3];
    const float* b_out = (const float*)d_in[4];
    float* out = (float*)d_out;

    void *xh_p = nullptr, *wqh_p = nullptr, *woh_p = nullptr, *oh_p = nullptr;
    cudaGetSymbolAddress(&xh_p, g_xh);
    cudaGetSymbolAddress(&wqh_p, g_wqh);
    cudaGetSymbolAddress(&woh_p, g_woh);
    cudaGetSymbolAddress(&oh_p, g_oh);

    static int attr_done = 0;
    if (!attr_done) {
        cudaFuncSetAttribute(gemm_h<1,0>, cudaFuncAttributeMaxDynamicSharedMemorySize, GEMM_SMEM);
        cudaFuncSetAttribute(gemm_h<0,1>, cudaFuncAttributeMaxDynamicSharedMemorySize, GEMM_SMEM);
        cudaFuncSetAttribute(flash_h,     cudaFuncAttributeMaxDynamicSharedMemorySize, FLASH_SMEM);
        attr_done = 1;
    }

    // 0) fp32 -> fp16 conversion of x, W_qkv, W_out
    cvt_kernel<<<512, 256>>>(x, W_qkv, W_out);

    // 1) QKV projection + bias + scatter into fp16 [B,H,T,D] (q pre-scaled)
    {
        dim3 grid((3 * DIMC) / 128, MROWS / 128);
        gemm_h<1,0><<<grid, 128, GEMM_SMEM>>>((const __half*)xh_p, (const __half*)wqh_p,
                                              b_qkv, nullptr, 3 * DIMC, DIMC);
    }
    // 2) Causal flash attention -> fp16 g_oh [B,T,C]
    {
        dim3 grid(SEQ / 128, BATCH * NH);
        flash_h<<<grid, 256, FLASH_SMEM>>>();
    }
    // 3) Output projection -> fp32 out (f16-accumulate probe)
    {
        dim3 grid(DIMC / 128, MROWS / 128);
        gemm_h<0,1><<<grid, 128, GEMM_SMEM>>>((const __half*)oh_p, (const __half*)woh_p,
                                              b_out, out, DIMC, DIMC);
    }
}

// round 10
// speedup vs baseline: 1.0347x; 1.0347x over previous
#include <cuda_runtime.h>
#include <cuda_fp16.h>
#include <math.h>
#include <stdint.h>

#define DIMC 1024
#define NH 16
#define HD 64
#define BATCH 4
#define SEQ 2048
#define MROWS (BATCH*SEQ)   // 8192
#define QSCALE 0.1803368801111204f   // log2(e)/8

// Scratch (device globals — no runtime allocation)
__device__ __half g_xh[(size_t)MROWS*DIMC];
__device__ __half g_wqh[(size_t)DIMC*3*DIMC];
__device__ __half g_woh[(size_t)DIMC*DIMC];
__device__ __half g_qh[(size_t)BATCH*NH*SEQ*HD];  // [B,H,T,D], pre-scaled by QSCALE
__device__ __half g_kh[(size_t)BATCH*NH*SEQ*HD];
__device__ __half g_vh[(size_t)BATCH*NH*SEQ*HD];
__device__ __half g_oh[(size_t)BATCH*SEQ*DIMC];   // attention out [B,T,C]

// ---------------------------------------------------------------------------
__device__ __forceinline__ void cp16(void* s, const void* g) {
    uint32_t a = (uint32_t)__cvta_generic_to_shared(s);
    asm volatile("cp.async.cg.shared.global [%0], [%1], 16;" :: "r"(a), "l"(g));
}
#define CP_COMMIT() asm volatile("cp.async.commit_group;" ::: "memory")
#define CP_WAIT0()  asm volatile("cp.async.wait_group 0;" ::: "memory")
#define CP_WAIT1()  asm volatile("cp.async.wait_group 1;" ::: "memory")

__device__ __forceinline__ void mma16(float c[4], const uint32_t a[4],
                                      uint32_t b0, uint32_t b1) {
    asm volatile(
        "mma.sync.aligned.m16n8k16.row.col.f32.f16.f16.f32 "
        "{%0,%1,%2,%3}, {%4,%5,%6,%7}, {%8,%9}, {%0,%1,%2,%3};\n"
        : "+f"(c[0]), "+f"(c[1]), "+f"(c[2]), "+f"(c[3])
        : "r"(a[0]), "r"(a[1]), "r"(a[2]), "r"(a[3]), "r"(b0), "r"(b1));
}
__device__ __forceinline__ void ldsm4(uint32_t r[4], const void* p) {
    uint32_t a = (uint32_t)__cvta_generic_to_shared(p);
    asm volatile("ldmatrix.sync.aligned.m8n8.x4.shared.b16 {%0,%1,%2,%3}, [%4];"
        : "=r"(r[0]), "=r"(r[1]), "=r"(r[2]), "=r"(r[3]) : "r"(a));
}
__device__ __forceinline__ void ldsm4t(uint32_t r[4], const void* p) {
    uint32_t a = (uint32_t)__cvta_generic_to_shared(p);
    asm volatile("ldmatrix.sync.aligned.m8n8.x4.trans.shared.b16 {%0,%1,%2,%3}, [%4];"
        : "=r"(r[0]), "=r"(r[1]), "=r"(r[2]), "=r"(r[3]) : "r"(a));
}
__device__ __forceinline__ uint32_t pexp2(float lo, float hi) {
    uint32_t h, r;
    asm("cvt.rn.f16x2.f32 %0, %1, %2;" : "=r"(h) : "f"(hi), "f"(lo));
    asm("ex2.approx.f16x2 %0, %1;" : "=r"(r) : "r"(h));
    return r;
}
__device__ __forceinline__ float fexp2(float x) {
    float r; asm("ex2.approx.f32 %0, %1;" : "=f"(r) : "f"(x)); return r;
}

// ---------------------------------------------------------------------------
// fp32 -> fp16 conversion pre-pass (x, W_qkv, W_out)
// ---------------------------------------------------------------------------
__global__ void cvt_kernel(const float* __restrict__ x, const float* __restrict__ wq,
                           const float* __restrict__ wo) {
    const int XN4 = MROWS * DIMC / 4;
    const int WQ4 = DIMC * 3 * DIMC / 4;
    const int WO4 = DIMC * DIMC / 4;
    const int total = XN4 + WQ4 + WO4;
    for (int i = blockIdx.x * blockDim.x + threadIdx.x; i < total;
         i += gridDim.x * blockDim.x) {
        const float4* src; __half2* dst; int j;
        if (i < XN4)            { src = (const float4*)x;  dst = (__half2*)g_xh;  j = i; }
        else if (i < XN4 + WQ4) { src = (const float4*)wq; dst = (__half2*)g_wqh; j = i - XN4; }
        else                    { src = (const float4*)wo; dst = (__half2*)g_woh; j = i - XN4 - WQ4; }
        float4 v = src[j];
        dst[2 * j]     = __floats2half2_rn(v.x, v.y);
        dst[2 * j + 1] = __floats2half2_rn(v.z, v.w);
    }
}

// ---------------------------------------------------------------------------
// fp16 mma GEMM: C[M,N] = A[M,K] @ W[K,N] + bias
// CTA 128x128, 128 threads (4 warps as 2m x 2n), warp tile 64x64.
// BK=64, 3-stage cp.async, double-buffered ldsm fragments. fp32 accumulate.
// ---------------------------------------------------------------------------
#define AS_STG (128 * 72)           // halves per A stage (pad 64+8)
#define BS_STG (64 * 136)           // halves per B stage (pad 128+8)
#define GEMM_SMEM ((3 * AS_STG + 3 * BS_STG) * 2)   // 107520 bytes

template<int SCATTER>
__global__ __launch_bounds__(128, 2) void gemm_h(
    const __half* __restrict__ Ah, const __half* __restrict__ Wh,
    const float* __restrict__ bias, float* __restrict__ C, int N, int K)
{
    extern __shared__ __align__(16) __half sm[];
    __half* As = sm;                   // [3][128][72]
    __half* Bs = sm + 3 * AS_STG;      // [3][64][136]

    const int tid  = threadIdx.x;
    const int wid  = tid >> 5;
    const int lane = tid & 31;
    const int gid  = lane >> 2;
    const int tig  = lane & 3;
    const int sel  = lane >> 3;
    const int lr   = lane & 7;
    const int wm   = wid & 1;     // 0..1
    const int wn   = wid >> 1;    // 0..1
    const int mBase = blockIdx.y * 128;
    const int nBase = blockIdx.x * 128;

    float acc[4][8][4];
    #pragma unroll
    for (int mt = 0; mt < 4; mt++)
        #pragma unroll
        for (int nt = 0; nt < 8; nt++)
            #pragma unroll
            for (int i = 0; i < 4; i++) acc[mt][nt][i] = 0.0f;

    const int NC = K / 64;   // 16

    #define ISSUE(c) do { \
        if ((c) < NC) { \
            const int kt = (c) * 64; \
            const int st = (c) % 3; \
            _Pragma("unroll") \
            for (int l = 0; l < 8; l++) { \
                const int o = tid + 128 * l; \
                cp16(&As[st * AS_STG + (o >> 3) * 72 + (o & 7) * 8], \
                     Ah + (size_t)(mBase + (o >> 3)) * K + kt + (o & 7) * 8); \
            } \
            _Pragma("unroll") \
            for (int l = 0; l < 8; l++) { \
                const int o = tid + 128 * l; \
                cp16(&Bs[st * BS_STG + (o >> 4) * 136 + (o & 15) * 8], \
                     Wh + (size_t)(kt + (o >> 4)) * N + nBase + (o & 15) * 8); \
            } \
        } \
        CP_COMMIT(); \
    } while (0)

    #define LDFRAG(s, kk, AF, BF) do { \
        _Pragma("unroll") \
        for (int mt = 0; mt < 4; mt++) \
            ldsm4(AF[mt], &As[(s) * AS_STG \
                              + (wm * 64 + mt * 16 + ((sel & 1) << 3) + lr) * 72 \
                              + (kk) * 16 + (sel >> 1) * 8]); \
        _Pragma("unroll") \
        for (int nb = 0; nb < 4; nb++) \
            ldsm4t(BF[nb], &Bs[(s) * BS_STG \
                               + ((kk) * 16 + (sel & 1) * 8 + lr) * 136 \
                               + wn * 64 + nb * 16 + (sel >> 1) * 8]); \
    } while (0)

    #define MMA32(AF, BF) do { \
        _Pragma("unroll") \
        for (int mt = 0; mt < 4; mt++) \
            _Pragma("unroll") \
            for (int nb = 0; nb < 4; nb++) { \
                mma16(acc[mt][2 * nb],     AF[mt], BF[nb][0], BF[nb][1]); \
                mma16(acc[mt][2 * nb + 1], AF[mt], BF[nb][2], BF[nb][3]); \
            } \
    } while (0)

    // Prologue: stages 0..1 in flight
    ISSUE(0); ISSUE(1);

    uint32_t af[2][4][4], bf[2][4][4];

    for (int c = 0; c < NC; c++) {
        const int s = c % 3;
        CP_WAIT1();            // stage c complete (pending = c+1)
        __syncthreads();       // all warps done reading slot being re-issued
        ISSUE(c + 2);
        LDFRAG(s, 0, af[0], bf[0]);
        #pragma unroll
        for (int kk = 0; kk < 4; kk++) {
            const int cur = kk & 1;
            if (kk < 3) LDFRAG(s, kk + 1, af[cur ^ 1], bf[cur ^ 1]);
            MMA32(af[cur], bf[cur]);
        }
    }
    #undef ISSUE
    #undef LDFRAG
    #undef MMA32

    // Epilogue
    #pragma unroll
    for (int mt = 0; mt < 4; mt++) {
        const int m0 = mBase + wm * 64 + mt * 16 + gid;
        #pragma unroll
        for (int nt = 0; nt < 8; nt++) {
            const int n = nBase + wn * 64 + nt * 8 + tig * 2;
            const float b0 = bias[n], b1 = bias[n + 1];
            float v0 = acc[mt][nt][0] + b0, v1 = acc[mt][nt][1] + b1;
            float v2 = acc[mt][nt][2] + b0, v3 = acc[mt][nt][3] + b1;
            if (SCATTER) {
                const int sec = n >> 10;
                const int cc  = n & 1023;
                const int h   = cc >> 6;
                const int d   = cc & 63;
                if (sec == 0) { v0 *= QSCALE; v1 *= QSCALE; v2 *= QSCALE; v3 *= QSCALE; }
                __half* dst = (sec == 0) ? g_qh : (sec == 1) ? g_kh : g_vh;
                const int m1 = m0 + 8;
                *(__half2*)&dst[(((size_t)(m0 >> 11) * NH + h) * SEQ + (m0 & (SEQ - 1))) * HD + d]
                    = __floats2half2_rn(v0, v1);
                *(__half2*)&dst[(((size_t)(m1 >> 11) * NH + h) * SEQ + (m1 & (SEQ - 1))) * HD + d]
                    = __floats2half2_rn(v2, v3);
            } else {
                *(float2*)&C[(size_t)m0 * N + n]       = make_float2(v0, v1);
                *(float2*)&C[(size_t)(m0 + 8) * N + n] = make_float2(v2, v3);
            }
        }
    }
}

// ---------------------------------------------------------------------------
// Causal flash attention, fp16 mma. CTA 256 threads (8 warps), BQ=128, BK=64.
// 3-stage cp.async K/V pipeline, ONE __syncthreads per tile.
// Row-sum l on ALU pipe (tensor pipe is the bottleneck); fully-masked
// diagonal sub-blocks skipped in both S and PV.
// ---------------------------------------------------------------------------
#define KV_STG (64 * 72)   // halves per stage per array
#define FLASH_SMEM ((3 * KV_STG + 3 * KV_STG) * 2)   // 55296 bytes

__global__ __launch_bounds__(256, 2) void flash_h()
{
    extern __shared__ __align__(16) __half fsm[];
    __half* Ks = fsm;                 // [3][64][72]
    __half* Vs = fsm + 3 * KV_STG;    // [3][64][72]

    const int tid  = threadIdx.x;
    const int warp = tid >> 5;
    const int lane = tid & 31;
    const int gid  = lane >> 2;
    const int tig  = lane & 3;
    const int sel  = lane >> 3;
    const int lr   = lane & 7;
    const int dw   = warp & 3;   // diag sub-block threshold within 64-row half
    const int bh = blockIdx.y;
    const int bb = bh >> 4;
    const int h  = bh & 15;
    const int q0 = blockIdx.x * 128;

    const __half* Qg = g_qh + (size_t)bh * SEQ * HD;
    const __half* Kg = g_kh + (size_t)bh * SEQ * HD;
    const __half* Vg = g_vh + (size_t)bh * SEQ * HD;

    // Stage Q (128 rows) into Ks stages 0-1, pull fragments, then release
    #pragma unroll
    for (int l = 0; l < 4; l++) {
        const int o = tid + 256 * l;
        const int row = o >> 3, seg = o & 7;
        cp16(&Ks[(row >> 6) * KV_STG + (row & 63) * 72 + seg * 8],
             Qg + (size_t)(q0 + row) * HD + seg * 8);
    }
    CP_COMMIT(); CP_WAIT0();
    __syncthreads();

    uint32_t qf[4][4];
    {
        const int rl = warp * 16 + ((sel & 1) << 3) + lr;  // 0..127
        #pragma unroll
        for (int kk = 0; kk < 4; kk++)
            ldsm4(qf[kk], &Ks[(rl >> 6) * KV_STG + (rl & 63) * 72
                              + kk * 16 + (sel >> 1) * 8]);
    }
    __syncthreads();

    float o_[8][4];
    #pragma unroll
    for (int nt = 0; nt < 8; nt++)
        #pragma unroll
        for (int i = 0; i < 4; i++) o_[nt][i] = 0.0f;
    float m0 = -1e30f, m1 = -1e30f, l0 = 0.0f, l1 = 0.0f;

    const int nT = (blockIdx.x + 1) * 2;

    #define ISSUE_KV(jt) do { \
        if ((jt) < nT) { \
            const int k0g = (jt) * 64; \
            const int st = (jt) % 3; \
            _Pragma("unroll") \
            for (int l = 0; l < 2; l++) { \
                const int o = tid + 256 * l; \
                const int row = o >> 3, seg = o & 7; \
                cp16(&Ks[st * KV_STG + row * 72 + seg * 8], \
                     Kg + (size_t)(k0g + row) * HD + seg * 8); \
            } \
            _Pragma("unroll") \
            for (int l = 0; l < 2; l++) { \
                const int o = tid + 256 * l; \
                const int row = o >> 3, seg = o & 7; \
                cp16(&Vs[st * KV_STG + row * 72 + seg * 8], \
                     Vg + (size_t)(k0g + row) * HD + seg * 8); \
            } \
        } \
        CP_COMMIT(); \
    } while (0)

    ISSUE_KV(0); ISSUE_KV(1);

    for (int jt = 0; jt < nT; jt++) {
        const int s = jt % 3;
        CP_WAIT1();            // tile jt complete (pending = jt+1)
        __syncthreads();       // readers of re-issued slot are done
        ISSUE_KV(jt + 2);

        // warps 0-3 (q rows q0..q0+63) skip the final k-tile entirely
        const bool act = !(warp < 4 && jt == nT - 1);
        if (act) {
            const bool diag = (warp < 4) ? (jt == nT - 2) : (jt == nT - 1);

            float sv[8][4];
            #pragma unroll
            for (int nt = 0; nt < 8; nt++)
                #pragma unroll
                for (int i = 0; i < 4; i++) sv[nt][i] = 0.0f;

            // S = Q~ K^T ; on diag tile skip fully-masked nb blocks (nb > dw)
            #pragma unroll
            for (int kk = 0; kk < 4; kk++)
                #pragma unroll
                for (int nb = 0; nb < 4; nb++) {
                    if (diag && nb > dw) continue;
                    uint32_t kf[4];
                    ldsm4(kf, &Ks[s * KV_STG
                                  + (nb * 16 + ((sel >> 1) << 3) + lr) * 72
                                  + kk * 16 + (sel & 1) * 8]);
                    mma16(sv[2 * nb],     qf[kk], kf[0], kf[1]);
                    mma16(sv[2 * nb + 1], qf[kk], kf[2], kf[3]);
                }

            if (diag) {
                const int qr = q0 + warp * 16 + gid;
                const int k0g = jt * 64;
                #pragma unroll
                for (int nt = 0; nt < 8; nt++) {
                    const int kc = k0g + nt * 8 + tig * 2;
                    if (kc > qr)         sv[nt][0] = -1e30f;
                    if (kc + 1 > qr)     sv[nt][1] = -1e30f;
                    if (kc > qr + 8)     sv[nt][2] = -1e30f;
                    if (kc + 1 > qr + 8) sv[nt][3] = -1e30f;
                }
            }

            float mx0 = -1e30f, mx1 = -1e30f;
            #pragma unroll
            for (int nt = 0; nt < 8; nt++) {
                mx0 = fmaxf(mx0, fmaxf(sv[nt][0], sv[nt][1]));
                mx1 = fmaxf(mx1, fmaxf(sv[nt][2], sv[nt][3]));
            }
            mx0 = fmaxf(mx0, __shfl_xor_sync(0xffffffffu, mx0, 1));
            mx0 = fmaxf(mx0, __shfl_xor_sync(0xffffffffu, mx0, 2));
            mx1 = fmaxf(mx1, __shfl_xor_sync(0xffffffffu, mx1, 1));
            mx1 = fmaxf(mx1, __shfl_xor_sync(0xffffffffu, mx1, 2));

            const float mn0 = fmaxf(m0, mx0);
            const float mn1 = fmaxf(m1, mx1);
            const float al0 = fexp2(m0 - mn0);
            const float al1 = fexp2(m1 - mn1);
            m0 = mn0; m1 = mn1;

            uint32_t pu[8][2];
            #pragma unroll
            for (int nt = 0; nt < 8; nt++) {
                pu[nt][0] = pexp2(sv[nt][0] - mn0, sv[nt][1] - mn0);
                pu[nt][1] = pexp2(sv[nt][2] - mn1, sv[nt][3] - mn1);
            }

            // Row-sum of the f16 P values on FMA/ALU pipe (tensor is bottleneck)
            float rs0 = 0.0f, rs1 = 0.0f;
            #pragma unroll
            for (int nt = 0; nt < 8; nt++) {
                float2 pa0 = __half22float2(*(__half2*)&pu[nt][0]);
                float2 pa1 = __half22float2(*(__half2*)&pu[nt][1]);
                rs0 += pa0.x + pa0.y;
                rs1 += pa1.x + pa1.y;
            }
            rs0 += __shfl_xor_sync(0xffffffffu, rs0, 1);
            rs0 += __shfl_xor_sync(0xffffffffu, rs0, 2);
            rs1 += __shfl_xor_sync(0xffffffffu, rs1, 1);
            rs1 += __shfl_xor_sync(0xffffffffu, rs1, 2);
            l0 = l0 * al0 + rs0;
            l1 = l1 * al1 + rs1;

            #pragma unroll
            for (int nt = 0; nt < 8; nt++) {
                o_[nt][0] *= al0; o_[nt][1] *= al0;
                o_[nt][2] *= al1; o_[nt][3] *= al1;
            }

            // O += P V ; on diag tile skip fully-masked kk chunks (kk > dw, P==0)
            #pragma unroll
            for (int kk = 0; kk < 4; kk++) {
                if (diag && kk > dw) continue;
                const uint32_t pa[4] = {pu[2 * kk][0], pu[2 * kk][1],
                                        pu[2 * kk + 1][0], pu[2 * kk + 1][1]};
                #pragma unroll
                for (int nb = 0; nb < 4; nb++) {
                    uint32_t vf[4];
                    ldsm4t(vf, &Vs[s * KV_STG
                                   + (kk * 16 + (sel & 1) * 8 + lr) * 72
                                   + nb * 16 + (sel >> 1) * 8]);
                    mma16(o_[2 * nb],     pa, vf[0], vf[1]);
                    mma16(o_[2 * nb + 1], pa, vf[2], vf[3]);
                }
            }
        }
    }
    #undef ISSUE_KV

    // Epilogue
    const float inv0 = 1.0f / l0;
    const float inv1 = 1.0f / l1;
    const int qr = q0 + warp * 16 + gid;
    __half* dst0 = g_oh + ((size_t)bb * SEQ + qr) * DIMC + h * HD;
    __half* dst1 = g_oh + ((size_t)bb * SEQ + qr + 8) * DIMC + h * HD;
    #pragma unroll
    for (int nt = 0; nt < 8; nt++) {
        const int d = nt * 8 + tig * 2;
        *(__half2*)&dst0[d] = __floats2half2_rn(o_[nt][0] * inv0, o_[nt][1] * inv0);
        *(__half2*)&dst1[d] = __floats2half2_rn(o_[nt][2] * inv1, o_[nt][3] * inv1);
    }
}

// ---------------------------------------------------------------------------
extern "C" void kernel_launch(void* const* d_in, const int* in_sizes, int n_in,
                              void* d_out, int out_size)
{
    const float* x     = (const float*)d_in[0];
    const float* W_qkv = (const float*)d_in[1];
    const float* b_qkv = (const float*)d_in[2];
    const float* W_out = (const float*)d_in[3];
    const float* b_out = (const float*)d_in[4];
    float* out = (float*)d_out;

    void *xh_p = nullptr, *wqh_p = nullptr, *woh_p = nullptr, *oh_p = nullptr;
    cudaGetSymbolAddress(&xh_p, g_xh);
    cudaGetSymbolAddress(&wqh_p, g_wqh);
    cudaGetSymbolAddress(&woh_p, g_woh);
    cudaGetSymbolAddress(&oh_p, g_oh);

    static int attr_done = 0;
    if (!attr_done) {
        cudaFuncSetAttribute(gemm_h<1>, cudaFuncAttributeMaxDynamicSharedMemorySize, GEMM_SMEM);
        cudaFuncSetAttribute(gemm_h<0>, cudaFuncAttributeMaxDynamicSharedMemorySize, GEMM_SMEM);
        cudaFuncSetAttribute(flash_h,   cudaFuncAttributeMaxDynamicSharedMemorySize, FLASH_SMEM);
        attr_done = 1;
    }

    // 0) fp32 -> fp16 conversion of x, W_qkv, W_out
    cvt_kernel<<<1024, 256>>>(x, W_qkv, W_out);

    // 1) QKV projection + bias + scatter into fp16 [B,H,T,D] (q pre-scaled)
    {
        dim3 grid((3 * DIMC) / 128, MROWS / 128);
        gemm_h<1><<<grid, 128, GEMM_SMEM>>>((const __half*)xh_p, (const __half*)wqh_p,
                                            b_qkv, nullptr, 3 * DIMC, DIMC);
    }
    // 2) Causal flash attention -> fp16 g_oh [B,T,C]
    {
        dim3 grid(SEQ / 128, BATCH * NH);
        flash_h<<<grid, 256, FLASH_SMEM>>>();
    }
    // 3) Output projection -> fp32 out
    {
        dim3 grid(DIMC / 128, MROWS / 128);
        gemm_h<0><<<grid, 128, GEMM_SMEM>>>((const __half*)oh_p, (const __half*)woh_p,
                                            b_out, out, DIMC, DIMC);
    }
}

// round 11
// speedup vs baseline: 1.0601x; 1.0245x over previous
#include <cuda_runtime.h>
#include <cuda_fp16.h>
#include <math.h>
#include <stdint.h>

#define DIMC 1024
#define NH 16
#define HD 64
#define BATCH 4
#define SEQ 2048
#define MROWS (BATCH*SEQ)   // 8192
#define QSCALE 0.1803368801111204f   // log2(e)/8

// Scratch (device globals — no runtime allocation)
__device__ __half g_xh[(size_t)MROWS*DIMC];
__device__ __half g_wqh[(size_t)DIMC*3*DIMC];
__device__ __half g_woh[(size_t)DIMC*DIMC];
__device__ __half g_qh[(size_t)BATCH*NH*SEQ*HD];  // [B,H,T,D], pre-scaled by QSCALE
__device__ __half g_kh[(size_t)BATCH*NH*SEQ*HD];
__device__ __half g_vh[(size_t)BATCH*NH*SEQ*HD];
__device__ __half g_oh[(size_t)BATCH*SEQ*DIMC];   // attention out [B,T,C]

// ---------------------------------------------------------------------------
__device__ __forceinline__ void cp16(void* s, const void* g) {
    uint32_t a = (uint32_t)__cvta_generic_to_shared(s);
    asm volatile("cp.async.cg.shared.global [%0], [%1], 16;" :: "r"(a), "l"(g));
}
#define CP_COMMIT() asm volatile("cp.async.commit_group;" ::: "memory")
#define CP_WAIT0()  asm volatile("cp.async.wait_group 0;" ::: "memory")
#define CP_WAIT1()  asm volatile("cp.async.wait_group 1;" ::: "memory")

__device__ __forceinline__ void mma16(float c[4], const uint32_t a[4],
                                      uint32_t b0, uint32_t b1) {
    asm volatile(
        "mma.sync.aligned.m16n8k16.row.col.f32.f16.f16.f32 "
        "{%0,%1,%2,%3}, {%4,%5,%6,%7}, {%8,%9}, {%0,%1,%2,%3};\n"
        : "+f"(c[0]), "+f"(c[1]), "+f"(c[2]), "+f"(c[3])
        : "r"(a[0]), "r"(a[1]), "r"(a[2]), "r"(a[3]), "r"(b0), "r"(b1));
}
__device__ __forceinline__ void ldsm4(uint32_t r[4], const void* p) {
    uint32_t a = (uint32_t)__cvta_generic_to_shared(p);
    asm volatile("ldmatrix.sync.aligned.m8n8.x4.shared.b16 {%0,%1,%2,%3}, [%4];"
        : "=r"(r[0]), "=r"(r[1]), "=r"(r[2]), "=r"(r[3]) : "r"(a));
}
__device__ __forceinline__ void ldsm4t(uint32_t r[4], const void* p) {
    uint32_t a = (uint32_t)__cvta_generic_to_shared(p);
    asm volatile("ldmatrix.sync.aligned.m8n8.x4.trans.shared.b16 {%0,%1,%2,%3}, [%4];"
        : "=r"(r[0]), "=r"(r[1]), "=r"(r[2]), "=r"(r[3]) : "r"(a));
}
__device__ __forceinline__ uint32_t pexp2(float lo, float hi) {
    uint32_t h, r;
    asm("cvt.rn.f16x2.f32 %0, %1, %2;" : "=r"(h) : "f"(hi), "f"(lo));
    asm("ex2.approx.f16x2 %0, %1;" : "=r"(r) : "r"(h));
    return r;
}
__device__ __forceinline__ float fexp2(float x) {
    float r; asm("ex2.approx.f32 %0, %1;" : "=f"(r) : "f"(x)); return r;
}

// ---------------------------------------------------------------------------
// fp32 -> fp16 conversion pre-pass (x, W_qkv, W_out)
// ---------------------------------------------------------------------------
__global__ void cvt_kernel(const float* __restrict__ x, const float* __restrict__ wq,
                           const float* __restrict__ wo) {
    const int XN4 = MROWS * DIMC / 4;
    const int WQ4 = DIMC * 3 * DIMC / 4;
    const int WO4 = DIMC * DIMC / 4;
    const int total = XN4 + WQ4 + WO4;
    for (int i = blockIdx.x * blockDim.x + threadIdx.x; i < total;
         i += gridDim.x * blockDim.x) {
        const float4* src; __half2* dst; int j;
        if (i < XN4)            { src = (const float4*)x;  dst = (__half2*)g_xh;  j = i; }
        else if (i < XN4 + WQ4) { src = (const float4*)wq; dst = (__half2*)g_wqh; j = i - XN4; }
        else                    { src = (const float4*)wo; dst = (__half2*)g_woh; j = i - XN4 - WQ4; }
        float4 v = src[j];
        dst[2 * j]     = __floats2half2_rn(v.x, v.y);
        dst[2 * j + 1] = __floats2half2_rn(v.z, v.w);
    }
}

// ---------------------------------------------------------------------------
// fp16 mma GEMM: C[M,N] = A[M,K] @ W[K,N] + bias
// CTA 128x128, 128 threads (4 warps as 2m x 2n), warp tile 64x64.
// BK=64, 3-stage cp.async, double-buffered ldsm fragments. fp32 accumulate.
// ---------------------------------------------------------------------------
#define AS_STG (128 * 72)           // halves per A stage (pad 64+8)
#define BS_STG (64 * 136)           // halves per B stage (pad 128+8)
#define GEMM_SMEM ((3 * AS_STG + 3 * BS_STG) * 2)   // 107520 bytes

template<int SCATTER>
__global__ __launch_bounds__(128, 2) void gemm_h(
    const __half* __restrict__ Ah, const __half* __restrict__ Wh,
    const float* __restrict__ bias, float* __restrict__ C, int N, int K)
{
    extern __shared__ __align__(16) __half sm[];
    __half* As = sm;                   // [3][128][72]
    __half* Bs = sm + 3 * AS_STG;      // [3][64][136]

    const int tid  = threadIdx.x;
    const int wid  = tid >> 5;
    const int lane = tid & 31;
    const int gid  = lane >> 2;
    const int tig  = lane & 3;
    const int sel  = lane >> 3;
    const int lr   = lane & 7;
    const int wm   = wid & 1;     // 0..1
    const int wn   = wid >> 1;    // 0..1
    const int mBase = blockIdx.y * 128;
    const int nBase = blockIdx.x * 128;

    float acc[4][8][4];
    #pragma unroll
    for (int mt = 0; mt < 4; mt++)
        #pragma unroll
        for (int nt = 0; nt < 8; nt++)
            #pragma unroll
            for (int i = 0; i < 4; i++) acc[mt][nt][i] = 0.0f;

    const int NC = K / 64;   // 16

    #define ISSUE(c) do { \
        if ((c) < NC) { \
            const int kt = (c) * 64; \
            const int st = (c) % 3; \
            _Pragma("unroll") \
            for (int l = 0; l < 8; l++) { \
                const int o = tid + 128 * l; \
                cp16(&As[st * AS_STG + (o >> 3) * 72 + (o & 7) * 8], \
                     Ah + (size_t)(mBase + (o >> 3)) * K + kt + (o & 7) * 8); \
            } \
            _Pragma("unroll") \
            for (int l = 0; l < 8; l++) { \
                const int o = tid + 128 * l; \
                cp16(&Bs[st * BS_STG + (o >> 4) * 136 + (o & 15) * 8], \
                     Wh + (size_t)(kt + (o >> 4)) * N + nBase + (o & 15) * 8); \
            } \
        } \
        CP_COMMIT(); \
    } while (0)

    #define LDFRAG(s, kk, AF, BF) do { \
        _Pragma("unroll") \
        for (int mt = 0; mt < 4; mt++) \
            ldsm4(AF[mt], &As[(s) * AS_STG \
                              + (wm * 64 + mt * 16 + ((sel & 1) << 3) + lr) * 72 \
                              + (kk) * 16 + (sel >> 1) * 8]); \
        _Pragma("unroll") \
        for (int nb = 0; nb < 4; nb++) \
            ldsm4t(BF[nb], &Bs[(s) * BS_STG \
                               + ((kk) * 16 + (sel & 1) * 8 + lr) * 136 \
                               + wn * 64 + nb * 16 + (sel >> 1) * 8]); \
    } while (0)

    #define MMA32(AF, BF) do { \
        _Pragma("unroll") \
        for (int mt = 0; mt < 4; mt++) \
            _Pragma("unroll") \
            for (int nb = 0; nb < 4; nb++) { \
                mma16(acc[mt][2 * nb],     AF[mt], BF[nb][0], BF[nb][1]); \
                mma16(acc[mt][2 * nb + 1], AF[mt], BF[nb][2], BF[nb][3]); \
            } \
    } while (0)

    // Prologue: stages 0..1 in flight
    ISSUE(0); ISSUE(1);

    uint32_t af[2][4][4], bf[2][4][4];

    for (int c = 0; c < NC; c++) {
        const int s = c % 3;
        CP_WAIT1();            // stage c complete (pending = c+1)
        __syncthreads();       // all warps done reading slot being re-issued
        ISSUE(c + 2);
        LDFRAG(s, 0, af[0], bf[0]);
        #pragma unroll
        for (int kk = 0; kk < 4; kk++) {
            const int cur = kk & 1;
            if (kk < 3) LDFRAG(s, kk + 1, af[cur ^ 1], bf[cur ^ 1]);
            MMA32(af[cur], bf[cur]);
        }
    }
    #undef ISSUE
    #undef LDFRAG
    #undef MMA32

    // Epilogue
    #pragma unroll
    for (int mt = 0; mt < 4; mt++) {
        const int m0 = mBase + wm * 64 + mt * 16 + gid;
        #pragma unroll
        for (int nt = 0; nt < 8; nt++) {
            const int n = nBase + wn * 64 + nt * 8 + tig * 2;
            const float b0 = bias[n], b1 = bias[n + 1];
            float v0 = acc[mt][nt][0] + b0, v1 = acc[mt][nt][1] + b1;
            float v2 = acc[mt][nt][2] + b0, v3 = acc[mt][nt][3] + b1;
            if (SCATTER) {
                const int sec = n >> 10;
                const int cc  = n & 1023;
                const int h   = cc >> 6;
                const int d   = cc & 63;
                if (sec == 0) { v0 *= QSCALE; v1 *= QSCALE; v2 *= QSCALE; v3 *= QSCALE; }
                __half* dst = (sec == 0) ? g_qh : (sec == 1) ? g_kh : g_vh;
                const int m1 = m0 + 8;
                *(__half2*)&dst[(((size_t)(m0 >> 11) * NH + h) * SEQ + (m0 & (SEQ - 1))) * HD + d]
                    = __floats2half2_rn(v0, v1);
                *(__half2*)&dst[(((size_t)(m1 >> 11) * NH + h) * SEQ + (m1 & (SEQ - 1))) * HD + d]
                    = __floats2half2_rn(v2, v3);
            } else {
                *(float2*)&C[(size_t)m0 * N + n]       = make_float2(v0, v1);
                *(float2*)&C[(size_t)(m0 + 8) * N + n] = make_float2(v2, v3);
            }
        }
    }
}

// ---------------------------------------------------------------------------
// Causal flash attention, fp16 mma. CTA 256 threads (8 warps), BQ=128, BK=64.
// 3-stage cp.async K/V pipeline, ONE __syncthreads per tile.
// LPT scheduling: longest CTAs (high q-blocks) launch first.
// ---------------------------------------------------------------------------
#define KV_STG (64 * 72)   // halves per stage per array
#define FLASH_SMEM ((3 * KV_STG + 3 * KV_STG) * 2)   // 55296 bytes

__global__ __launch_bounds__(256, 2) void flash_h()
{
    extern __shared__ __align__(16) __half fsm[];
    __half* Ks = fsm;                 // [3][64][72]
    __half* Vs = fsm + 3 * KV_STG;    // [3][64][72]

    const int tid  = threadIdx.x;
    const int warp = tid >> 5;
    const int lane = tid & 31;
    const int gid  = lane >> 2;
    const int tig  = lane & 3;
    const int sel  = lane >> 3;
    const int lr   = lane & 7;
    const int bh = blockIdx.y;
    const int bb = bh >> 4;
    const int h  = bh & 15;
    const int qb = gridDim.x - 1 - blockIdx.x;   // LPT: big q-blocks first
    const int q0 = qb * 128;

    const __half* Qg = g_qh + (size_t)bh * SEQ * HD;
    const __half* Kg = g_kh + (size_t)bh * SEQ * HD;
    const __half* Vg = g_vh + (size_t)bh * SEQ * HD;

    // Stage Q (128 rows) into Ks stages 0-1, pull fragments, then release
    #pragma unroll
    for (int l = 0; l < 4; l++) {
        const int o = tid + 256 * l;
        const int row = o >> 3, seg = o & 7;
        cp16(&Ks[(row >> 6) * KV_STG + (row & 63) * 72 + seg * 8],
             Qg + (size_t)(q0 + row) * HD + seg * 8);
    }
    CP_COMMIT(); CP_WAIT0();
    __syncthreads();

    uint32_t qf[4][4];
    {
        const int rl = warp * 16 + ((sel & 1) << 3) + lr;  // 0..127
        #pragma unroll
        for (int kk = 0; kk < 4; kk++)
            ldsm4(qf[kk], &Ks[(rl >> 6) * KV_STG + (rl & 63) * 72
                              + kk * 16 + (sel >> 1) * 8]);
    }
    __syncthreads();

    float o_[8][4], lac[4];
    #pragma unroll
    for (int nt = 0; nt < 8; nt++)
        #pragma unroll
        for (int i = 0; i < 4; i++) o_[nt][i] = 0.0f;
    #pragma unroll
    for (int i = 0; i < 4; i++) lac[i] = 0.0f;
    float m0 = -1e30f, m1 = -1e30f;

    const int nT = (qb + 1) * 2;

    #define ISSUE_KV(jt) do { \
        if ((jt) < nT) { \
            const int k0g = (jt) * 64; \
            const int st = (jt) % 3; \
            _Pragma("unroll") \
            for (int l = 0; l < 2; l++) { \
                const int o = tid + 256 * l; \
                const int row = o >> 3, seg = o & 7; \
                cp16(&Ks[st * KV_STG + row * 72 + seg * 8], \
                     Kg + (size_t)(k0g + row) * HD + seg * 8); \
            } \
            _Pragma("unroll") \
            for (int l = 0; l < 2; l++) { \
                const int o = tid + 256 * l; \
                const int row = o >> 3, seg = o & 7; \
                cp16(&Vs[st * KV_STG + row * 72 + seg * 8], \
                     Vg + (size_t)(k0g + row) * HD + seg * 8); \
            } \
        } \
        CP_COMMIT(); \
    } while (0)

    ISSUE_KV(0); ISSUE_KV(1);

    for (int jt = 0; jt < nT; jt++) {
        const int s = jt % 3;
        CP_WAIT1();            // tile jt complete (pending = jt+1)
        __syncthreads();       // readers of re-issued slot are done
        ISSUE_KV(jt + 2);

        // warps 0-3 (q rows q0..q0+63) skip the final k-tile entirely
        const bool act = !(warp < 4 && jt == nT - 1);
        if (act) {
            float sv[8][4];
            #pragma unroll
            for (int nt = 0; nt < 8; nt++)
                #pragma unroll
                for (int i = 0; i < 4; i++) sv[nt][i] = 0.0f;

            #pragma unroll
            for (int kk = 0; kk < 4; kk++)
                #pragma unroll
                for (int nb = 0; nb < 4; nb++) {
                    uint32_t kf[4];
                    ldsm4(kf, &Ks[s * KV_STG
                                  + (nb * 16 + ((sel >> 1) << 3) + lr) * 72
                                  + kk * 16 + (sel & 1) * 8]);
                    mma16(sv[2 * nb],     qf[kk], kf[0], kf[1]);
                    mma16(sv[2 * nb + 1], qf[kk], kf[2], kf[3]);
                }

            const bool diag = (warp < 4) ? (jt == nT - 2) : (jt == nT - 1);
            if (diag) {
                const int qr = q0 + warp * 16 + gid;
                const int k0g = jt * 64;
                #pragma unroll
                for (int nt = 0; nt < 8; nt++) {
                    const int kc = k0g + nt * 8 + tig * 2;
                    if (kc > qr)         sv[nt][0] = -1e30f;
                    if (kc + 1 > qr)     sv[nt][1] = -1e30f;
                    if (kc > qr + 8)     sv[nt][2] = -1e30f;
                    if (kc + 1 > qr + 8) sv[nt][3] = -1e30f;
                }
            }

            float mx0 = -1e30f, mx1 = -1e30f;
            #pragma unroll
            for (int nt = 0; nt < 8; nt++) {
                mx0 = fmaxf(mx0, fmaxf(sv[nt][0], sv[nt][1]));
                mx1 = fmaxf(mx1, fmaxf(sv[nt][2], sv[nt][3]));
            }
            mx0 = fmaxf(mx0, __shfl_xor_sync(0xffffffffu, mx0, 1));
            mx0 = fmaxf(mx0, __shfl_xor_sync(0xffffffffu, mx0, 2));
            mx1 = fmaxf(mx1, __shfl_xor_sync(0xffffffffu, mx1, 1));
            mx1 = fmaxf(mx1, __shfl_xor_sync(0xffffffffu, mx1, 2));

            const float mn0 = fmaxf(m0, mx0);
            const float mn1 = fmaxf(m1, mx1);
            const float al0 = fexp2(m0 - mn0);
            const float al1 = fexp2(m1 - mn1);
            m0 = mn0; m1 = mn1;

            uint32_t pu[8][2];
            #pragma unroll
            for (int nt = 0; nt < 8; nt++) {
                pu[nt][0] = pexp2(sv[nt][0] - mn0, sv[nt][1] - mn0);
                pu[nt][1] = pexp2(sv[nt][2] - mn1, sv[nt][3] - mn1);
            }

            #pragma unroll
            for (int nt = 0; nt < 8; nt++) {
                o_[nt][0] *= al0; o_[nt][1] *= al0;
                o_[nt][2] *= al1; o_[nt][3] *= al1;
            }
            lac[0] *= al0; lac[1] *= al0; lac[2] *= al1; lac[3] *= al1;

            const uint32_t ones = 0x3C003C00u;
            #pragma unroll
            for (int kk = 0; kk < 4; kk++) {
                const uint32_t pa[4] = {pu[2 * kk][0], pu[2 * kk][1],
                                        pu[2 * kk + 1][0], pu[2 * kk + 1][1]};
                mma16(lac, pa, ones, ones);
                #pragma unroll
                for (int nb = 0; nb < 4; nb++) {
                    uint32_t vf[4];
                    ldsm4t(vf, &Vs[s * KV_STG
                                   + (kk * 16 + (sel & 1) * 8 + lr) * 72
                                   + nb * 16 + (sel >> 1) * 8]);
                    mma16(o_[2 * nb],     pa, vf[0], vf[1]);
                    mma16(o_[2 * nb + 1], pa, vf[2], vf[3]);
                }
            }
        }
    }
    #undef ISSUE_KV

    // Epilogue
    const float inv0 = 1.0f / lac[0];
    const float inv1 = 1.0f / lac[2];
    const int qr = q0 + warp * 16 + gid;
    __half* dst0 = g_oh + ((size_t)bb * SEQ + qr) * DIMC + h * HD;
    __half* dst1 = g_oh + ((size_t)bb * SEQ + qr + 8) * DIMC + h * HD;
    #pragma unroll
    for (int nt = 0; nt < 8; nt++) {
        const int d = nt * 8 + tig * 2;
        *(__half2*)&dst0[d] = __floats2half2_rn(o_[nt][0] * inv0, o_[nt][1] * inv0);
        *(__half2*)&dst1[d] = __floats2half2_rn(o_[nt][2] * inv1, o_[nt][3] * inv1);
    }
}

// ---------------------------------------------------------------------------
extern "C" void kernel_launch(void* const* d_in, const int* in_sizes, int n_in,
                              void* d_out, int out_size)
{
    const float* x     = (const float*)d_in[0];
    const float* W_qkv = (const float*)d_in[1];
    const float* b_qkv = (const float*)d_in[2];
    const float* W_out = (const float*)d_in[3];
    const float* b_out = (const float*)d_in[4];
    float* out = (float*)d_out;

    void *xh_p = nullptr, *wqh_p = nullptr, *woh_p = nullptr, *oh_p = nullptr;
    cudaGetSymbolAddress(&xh_p, g_xh);
    cudaGetSymbolAddress(&wqh_p, g_wqh);
    cudaGetSymbolAddress(&woh_p, g_woh);
    cudaGetSymbolAddress(&oh_p, g_oh);

    static int attr_done = 0;
    if (!attr_done) {
        cudaFuncSetAttribute(gemm_h<1>, cudaFuncAttributeMaxDynamicSharedMemorySize, GEMM_SMEM);
        cudaFuncSetAttribute(gemm_h<0>, cudaFuncAttributeMaxDynamicSharedMemorySize, GEMM_SMEM);
        cudaFuncSetAttribute(flash_h,   cudaFuncAttributeMaxDynamicSharedMemorySize, FLASH_SMEM);
        attr_done = 1;
    }

    // 0) fp32 -> fp16 conversion of x, W_qkv, W_out
    cvt_kernel<<<512, 256>>>(x, W_qkv, W_out);

    // 1) QKV projection + bias + scatter into fp16 [B,H,T,D] (q pre-scaled)
    {
        dim3 grid((3 * DIMC) / 128, MROWS / 128);
        gemm_h<1><<<grid, 128, GEMM_SMEM>>>((const __half*)xh_p, (const __half*)wqh_p,
                                            b_qkv, nullptr, 3 * DIMC, DIMC);
    }
    // 2) Causal flash attention -> fp16 g_oh [B,T,C]
    {
        dim3 grid(SEQ / 128, BATCH * NH);
        flash_h<<<grid, 256, FLASH_SMEM>>>();
    }
    // 3) Output projection -> fp32 out
    {
        dim3 grid(DIMC / 128, MROWS / 128);
        gemm_h<0><<<grid, 128, GEMM_SMEM>>>((const __half*)oh_p, (const __half*)woh_p,
                                            b_out, out, DIMC, DIMC);
    }
}